// round 12
// baseline (speedup 1.0000x reference)
#include <cuda_runtime.h>
#include <cuda_bf16.h>

#define N_NODES 50000
#define E_EDGES 600000
#define FDIM    128
#define HDIM    16
#define NBLK    296          // 2 blocks/SM x 148 SMs — wave-1 co-resident
#define NTHR    256
#define GSTRIDE (NBLK * NTHR)

// device state (referenced ONLY in device code).
// g_deg/g_acc1/g_acc2 are 0 at rest; consumer phases reset them (replay-safe).
__device__ float             g_deg [N_NODES];
__device__ float             g_dinv[N_NODES];
__device__ float             g_h   [N_NODES * HDIM];   // h1s then z1s
__device__ float             g_acc1[N_NODES * HDIM];
__device__ float             g_acc2[N_NODES * HDIM];
__device__ unsigned          g_bar_count;               // 0 at rest
__device__ volatile unsigned g_bar_gen;                 // monotonic

__device__ __forceinline__ int load_edge_idx(const unsigned int* __restrict__ ei,
                                             int mode, int pos) {
    if (mode == 1) return (int)ei[2 * pos];             // int64: low word
    unsigned int v = ei[pos];
    if (mode == 2) return (int)__int_as_float((int)v);  // float32-encoded
    return (int)v;                                      // int32
}

__device__ __forceinline__ void red_add_f4(float* addr, float4 v) {
    asm volatile("red.global.add.v4.f32 [%0], {%1,%2,%3,%4};"
                 :: "l"(addr), "f"(v.x), "f"(v.y), "f"(v.z), "f"(v.w) : "memory");
}

// sense-reversing grid barrier (all NBLK blocks co-resident by construction)
__device__ __forceinline__ void grid_barrier() {
    __syncthreads();
    if (threadIdx.x == 0) {
        __threadfence();                      // publish this block's writes
        unsigned gen = g_bar_gen;             // read BEFORE arriving
        if (atomicAdd(&g_bar_count, 1u) == NBLK - 1) {
            g_bar_count = 0;
            __threadfence();
            g_bar_gen = gen + 1u;             // release
        } else {
            while (g_bar_gen == gen) { }      // spin (volatile)
        }
        __threadfence();                      // acquire
    }
    __syncthreads();
}

__global__ void __launch_bounds__(NTHR, 2)
gcn_kernel(const float* __restrict__ x, const unsigned int* __restrict__ ei,
           const float* __restrict__ W1, const float* __restrict__ b1,
           const float* __restrict__ W2, const float* __restrict__ b2,
           float* __restrict__ out) {
    __shared__ float sw[FDIM * HDIM + FDIM];   // W1, later W2|b2 (8.7 KB)
    const int tid  = threadIdx.x;
    const int gid0 = blockIdx.x * NTHR + tid;

    // ---- phase 0 (per-block, no sync needed): detect edge dtype ----
    int mode;
    {
        __shared__ int s_big, s_odd;
        if (tid == 0) { s_big = 0; s_odd = 0; }
        __syncthreads();
        int big = 0, odd = 0;
        for (int k = tid; k < 4096; k += NTHR) {
            unsigned int v = ei[k];
            if (v >= 0x30000000u) big++;
            if ((k & 1) && v != 0u) odd++;
        }
#pragma unroll
        for (int o = 16; o; o >>= 1) {
            big += __shfl_xor_sync(0xFFFFFFFFu, big, o);
            odd += __shfl_xor_sync(0xFFFFFFFFu, odd, o);
        }
        if ((tid & 31) == 0) {
            if (big) atomicAdd(&s_big, big);
            if (odd) atomicAdd(&s_odd, odd);
        }
        __syncthreads();
        mode = (s_big > 1024) ? 2 : ((s_odd == 0) ? 1 : 0);
    }

    // ---- phase 1: degree count over targets ----
    for (int e = gid0; e < E_EDGES; e += GSTRIDE) {
        int c = load_edge_idx(ei, mode, E_EDGES + e);
        if ((unsigned)c < (unsigned)N_NODES)
            atomicAdd(&g_deg[c], 1.0f);
    }
    grid_barrier();   // 1

    // ---- phase 2: h1s = dinv*(x@W1); publish dinv; reset deg ----
    for (int i = tid; i < FDIM * HDIM; i += NTHR) sw[i] = W1[i];
    __syncthreads();
    for (int g = gid0; g < N_NODES * 4; g += GSTRIDE) {
        int row = g >> 2;
        int jg  = (g & 3) * 4;
        float dinv = rsqrtf(g_deg[row] + 1.0f);   // +1 = self-loop

        const float4* xr = (const float4*)(x + (size_t)row * FDIM);
        float4 acc = make_float4(0.f, 0.f, 0.f, 0.f);
#pragma unroll
        for (int k4 = 0; k4 < FDIM / 4; k4++) {
            float4 xv = xr[k4];
            float4 w0 = *(const float4*)&sw[(k4 * 4 + 0) * HDIM + jg];
            float4 w1 = *(const float4*)&sw[(k4 * 4 + 1) * HDIM + jg];
            float4 w2 = *(const float4*)&sw[(k4 * 4 + 2) * HDIM + jg];
            float4 w3 = *(const float4*)&sw[(k4 * 4 + 3) * HDIM + jg];
            acc.x += xv.x * w0.x + xv.y * w1.x + xv.z * w2.x + xv.w * w3.x;
            acc.y += xv.x * w0.y + xv.y * w1.y + xv.z * w2.y + xv.w * w3.y;
            acc.z += xv.x * w0.z + xv.y * w1.z + xv.z * w2.z + xv.w * w3.z;
            acc.w += xv.x * w0.w + xv.y * w1.w + xv.z * w2.w + xv.w * w3.w;
        }
        acc.x *= dinv; acc.y *= dinv; acc.z *= dinv; acc.w *= dinv;
        *(float4*)(g_h + row * HDIM + jg) = acc;
        if (jg == 0) {
            g_dinv[row] = dinv;
            g_deg[row]  = 0.0f;   // self-clean (all 4 readers are in this warp, reads precede)
        }
    }
    grid_barrier();   // 2

    // ---- phase 3: layer-1 scatter: acc1[c] += h1s[r] ----
    for (int e = gid0; e < E_EDGES; e += GSTRIDE) {
        int r = load_edge_idx(ei, mode, e);
        int c = load_edge_idx(ei, mode, E_EDGES + e);
        if ((unsigned)r < (unsigned)N_NODES && (unsigned)c < (unsigned)N_NODES) {
            const float4* hr = (const float4*)(g_h + r * HDIM);
            float*        ac = g_acc1 + c * HDIM;
#pragma unroll
            for (int p = 0; p < HDIM / 4; p++)
                red_add_f4(ac + p * 4, hr[p]);
        }
    }
    grid_barrier();   // 3

    // ---- phase 4: z1s = dinv*relu(dinv*(acc1+h1s)+b1); reset acc1 ----
    for (int idx = gid0; idx < N_NODES * HDIM; idx += GSTRIDE) {
        int j    = idx & 15;
        int node = idx >> 4;
        float dinv = g_dinv[node];
        float z = fmaxf(dinv * (g_acc1[idx] + g_h[idx]) + b1[j], 0.0f);
        g_h[idx]    = dinv * z;
        g_acc1[idx] = 0.0f;
    }
    grid_barrier();   // 4

    // ---- phase 5: layer-2 scatter: acc2[c] += z1s[r] ----
    for (int e = gid0; e < E_EDGES; e += GSTRIDE) {
        int r = load_edge_idx(ei, mode, e);
        int c = load_edge_idx(ei, mode, E_EDGES + e);
        if ((unsigned)r < (unsigned)N_NODES && (unsigned)c < (unsigned)N_NODES) {
            const float4* hr = (const float4*)(g_h + r * HDIM);
            float*        ac = g_acc2 + c * HDIM;
#pragma unroll
            for (int p = 0; p < HDIM / 4; p++)
                red_add_f4(ac + p * 4, hr[p]);
        }
    }
    grid_barrier();   // 5

    // ---- phase 6: out = log_softmax(dinv*(acc2+z1s) @ W2 + b2); reset acc2 ----
    for (int i = tid; i < FDIM * HDIM; i += NTHR) sw[i] = W2[i];
    for (int i = tid; i < FDIM; i += NTHR)        sw[FDIM * HDIM + i] = b2[i];
    __syncthreads();

    const int warp0  = blockIdx.x * (NTHR / 32) + (tid >> 5);
    const int lane   = tid & 31;
    const int nwarps = NBLK * (NTHR / 32);

    for (int node = warp0; node < N_NODES; node += nwarps) {
        float dinv = g_dinv[node];
        const float* ar = g_acc2 + node * HDIM;
        const float* zr = g_h    + node * HDIM;
        float a[HDIM];
#pragma unroll
        for (int k = 0; k < HDIM; k++)
            a[k] = dinv * (ar[k] + zr[k]);   // reads done before the reset below

        if (lane < 4)
            *(float4*)(g_acc2 + node * HDIM + lane * 4) = make_float4(0.f, 0.f, 0.f, 0.f);

        int c0 = lane * 4;
        float o0 = sw[FDIM * HDIM + c0 + 0], o1 = sw[FDIM * HDIM + c0 + 1];
        float o2 = sw[FDIM * HDIM + c0 + 2], o3 = sw[FDIM * HDIM + c0 + 3];
#pragma unroll
        for (int k = 0; k < HDIM; k++) {
            float4 w = *(const float4*)&sw[k * FDIM + c0];
            o0 += a[k] * w.x; o1 += a[k] * w.y; o2 += a[k] * w.z; o3 += a[k] * w.w;
        }

        float m = fmaxf(fmaxf(o0, o1), fmaxf(o2, o3));
#pragma unroll
        for (int off = 16; off > 0; off >>= 1)
            m = fmaxf(m, __shfl_xor_sync(0xFFFFFFFFu, m, off));

        float s = expf(o0 - m) + expf(o1 - m) + expf(o2 - m) + expf(o3 - m);
#pragma unroll
        for (int off = 16; off > 0; off >>= 1)
            s += __shfl_xor_sync(0xFFFFFFFFu, s, off);
        float lse = m + logf(s);

        float4 r = make_float4(o0 - lse, o1 - lse, o2 - lse, o3 - lse);
        *(float4*)(out + (size_t)node * FDIM + c0) = r;
    }
}

extern "C" void kernel_launch(void* const* d_in, const int* in_sizes, int n_in,
                              void* d_out, int out_size) {
    const float*        x  = nullptr;
    const unsigned int* ei = nullptr;
    const float*        W1 = nullptr;
    const float*        W2 = nullptr;
    const float*        b1 = nullptr;
    const float*        b2 = nullptr;

    for (int i = 0; i < n_in; i++) {
        long long sz = in_sizes[i];
        if (sz == 6400000LL || sz == 25600000LL)        x  = (const float*)d_in[i];
        else if (sz == 1200000LL || sz == 2400000LL ||
                 sz == 4800000LL || sz == 9600000LL)     ei = (const unsigned int*)d_in[i];
        else if (sz == 2048LL || sz == 8192LL) { if (!W1) W1 = (const float*)d_in[i];
                                                 else     W2 = (const float*)d_in[i]; }
        else if (sz == 16LL  || sz == 64LL)              b1 = (const float*)d_in[i];
        else if (sz == 128LL || sz == 512LL)             b2 = (const float*)d_in[i];
    }
    if (!x)  x  = (const float*)d_in[0];
    if (!ei) ei = (const unsigned int*)d_in[1];
    if (!W1) W1 = (const float*)d_in[2];
    if (!b1) b1 = (const float*)d_in[3];
    if (!W2) W2 = (const float*)d_in[4];
    if (!b2) b2 = (const float*)d_in[5];

    gcn_kernel<<<NBLK, NTHR>>>(x, ei, W1, b1, W2, b2, (float*)d_out);
}